// round 14
// baseline (speedup 1.0000x reference)
#include <cuda_runtime.h>
#include <cstdint>

// ---------------------------------------------------------------------------
// ImageGraphConvolution:
//   support = x @ W + b                      [N,1024] @ [1024,14] + [14]
//   out[r]  = sum_e{row[e]==r} vals[e] * support[col[e]]   (COO segment-sum)
//
// R13:
//   - persistent GEMM grid (296 = 2 CTA/SM x 148 SMs), W in smem, cp.async
//     double-buffered x, packed fma.rn.f32x2.
//   - SpMM rewritten as sort-free CSR: count -> 2-level scan -> bin ->
//     warp-per-row gather-reduce. ZERO float atomics (the R11 profile gap
//     is explained by L2 atomic-ALU serialization of 44.8M float REDs).
//   - gather writes d_out directly (compact kernel and out_pad eliminated).
// ---------------------------------------------------------------------------

#define FEAT 1024
#define ODIM 14
#define PAD  16          // padded support row stride (floats) -> 64B
#define TPB  128         // threads per block (GEMM)
#define RPT  2
#define RPB  (TPB * RPT) // 256 rows per block
#define KB   16          // k-chunk staged through smem
#define XS_STRIDE (KB + 4)
#define STAGE_OPS ((RPB * KB / 4) / TPB)

#define W_FLOATS (ODIM * FEAT)                         // 14336
#define XS_FLOATS (RPB * XS_STRIDE)                    // 5120 per buffer
#define GEMM_SMEM_BYTES ((W_FLOATS + 2 * XS_FLOATS) * 4)  // 98304 B
#define GEMM_GRID 296

#define MAXN 100000
#define MAXE 3250000
#define SCAN_CHUNK 512   // rows per scan block

// Scratch (no allocation allowed -> __device__ globals)
__device__ __align__(16) float    g_support[MAXN * PAD];   // 6.4 MB
__device__ __align__(16) float    g_Wt[W_FLOATS];
__device__ unsigned               g_cnt[MAXN];
__device__ unsigned               g_rowstart[MAXN + 1];
__device__ unsigned               g_cursor[MAXN];
__device__ unsigned               g_partials[256];
__device__ __align__(8) uint2     g_bins[MAXE];            // (val bits, col)

// ---- packed f32x2 FMA ----
__device__ __forceinline__ unsigned long long pk2(float lo, float hi) {
    unsigned long long r;
    asm("mov.b64 %0, {%1, %2};" : "=l"(r) : "f"(lo), "f"(hi));
    return r;
}
__device__ __forceinline__ void fma2(unsigned long long& d,
                                     unsigned long long a,
                                     unsigned long long b) {
    asm("fma.rn.f32x2 %0, %1, %2, %0;" : "+l"(d) : "l"(a), "l"(b));
}
__device__ __forceinline__ float sum2(unsigned long long v) {
    float lo, hi;
    asm("mov.b64 {%0, %1}, %2;" : "=f"(lo), "=f"(hi) : "l"(v));
    return lo + hi;
}

// ---- cp.async 16B ----
__device__ __forceinline__ void cp_async16(void* smem_dst, const void* gsrc) {
    uint32_t d = (uint32_t)__cvta_generic_to_shared(smem_dst);
    asm volatile("cp.async.ca.shared.global [%0], [%1], 16;"
                 :: "r"(d), "l"(gsrc));
}
__device__ __forceinline__ void cp_commit() {
    asm volatile("cp.async.commit_group;");
}
template <int N>
__device__ __forceinline__ void cp_wait() {
    asm volatile("cp.async.wait_group %0;" :: "n"(N));
}

// ---------------------------------------------------------------------------
__global__ void transpose_w_kernel(const float* __restrict__ W) {
    int i = blockIdx.x * blockDim.x + threadIdx.x;
    if (i < ODIM * FEAT) {
        int j = i / FEAT;
        int k = i % FEAT;
        g_Wt[i] = W[k * ODIM + j];
    }
}

__global__ void zero_cnt_kernel(int nrows) {
    int i = blockIdx.x * blockDim.x + threadIdx.x;
    if (i < nrows) g_cnt[i] = 0u;
}

// ---------------------------------------------------------------------------
// GEMM (persistent): 2 rows/thread, W in smem, cp.async double buffer.
// ---------------------------------------------------------------------------
__global__ void __launch_bounds__(TPB)
gemm_kernel(const float* __restrict__ x, const float* __restrict__ b, int nrows) {
    extern __shared__ __align__(16) float smem[];
    float* Ws  = smem;
    float* xs0 = smem + W_FLOATS;
    float* xs1 = xs0 + XS_FLOATS;

    const int t = threadIdx.x;

#pragma unroll 4
    for (int i = t; i < W_FLOATS / 4; i += TPB)
        ((float4*)Ws)[i] = ((const float4*)g_Wt)[i];

    float bias[ODIM];
#pragma unroll
    for (int j = 0; j < ODIM; j++) bias[j] = __ldg(b + j);

    const int ntiles = (nrows + RPB - 1) / RPB;

    for (int tile = blockIdx.x; tile < ntiles; tile += gridDim.x) {
        const int row0 = tile * RPB;
        const int rA   = row0 + t;
        const int rB   = row0 + TPB + t;

        auto issue_stage = [&](float* bufp, int k0) {
#pragma unroll
            for (int i = 0; i < STAGE_OPS; i++) {
                int idx = i * TPB + t;
                int r = idx >> 2;
                int q = idx & 3;
                int gr = row0 + r;
                if (gr >= nrows) gr = nrows - 1;   // clamp; discarded later
                cp_async16(bufp + r * XS_STRIDE + q * 4,
                           x + (size_t)gr * FEAT + k0 + q * 4);
            }
            cp_commit();
        };

        unsigned long long accA[ODIM], accB[ODIM];
#pragma unroll
        for (int j = 0; j < ODIM; j++) { accA[j] = 0ull; accB[j] = 0ull; }

        issue_stage(xs0, 0);

        int buf = 0;
        for (int k0 = 0; k0 < FEAT; k0 += KB, buf ^= 1) {
            if (k0 + KB < FEAT) {
                issue_stage(buf ? xs0 : xs1, k0 + KB);
                cp_wait<1>();
            } else {
                cp_wait<0>();
            }
            __syncthreads();

            const float* xsc = buf ? xs1 : xs0;
#pragma unroll
            for (int kk = 0; kk < KB; kk += 4) {
                float4 xa = *(const float4*)(xsc + t * XS_STRIDE + kk);
                float4 xb = *(const float4*)(xsc + (TPB + t) * XS_STRIDE + kk);
                unsigned long long xa0 = pk2(xa.x, xa.y), xa1 = pk2(xa.z, xa.w);
                unsigned long long xb0 = pk2(xb.x, xb.y), xb1 = pk2(xb.z, xb.w);
#pragma unroll
                for (int j = 0; j < ODIM; j++) {
                    float4 w = *(const float4*)(Ws + j * FEAT + k0 + kk);
                    unsigned long long w0 = pk2(w.x, w.y), w1 = pk2(w.z, w.w);
                    fma2(accA[j], xa0, w0);
                    fma2(accA[j], xa1, w1);
                    fma2(accB[j], xb0, w0);
                    fma2(accB[j], xb1, w1);
                }
            }
            __syncthreads();
        }

        if (rA < nrows) {
            float* s = g_support + (size_t)rA * PAD;
#pragma unroll
            for (int j = 0; j < ODIM; j++)
                s[j] = sum2(accA[j]) + bias[j];
            s[14] = 0.f; s[15] = 0.f;
        }
        if (rB < nrows) {
            float* s = g_support + (size_t)rB * PAD;
#pragma unroll
            for (int j = 0; j < ODIM; j++)
                s[j] = sum2(accB[j]) + bias[j];
            s[14] = 0.f; s[15] = 0.f;
        }
    }
}

// ---------------------------------------------------------------------------
// CSR build: count -> partial sums -> scan partials -> offsets -> bin
// ---------------------------------------------------------------------------
__global__ void __launch_bounds__(256)
count_kernel(const int* __restrict__ rows, int nE) {
    int e = blockIdx.x * blockDim.x + threadIdx.x;
    if (e < nE)
        atomicAdd(&g_cnt[__ldg(rows + e)], 1u);   // result unused -> RED
}

__global__ void __launch_bounds__(256)
partial_kernel(int nrows) {
    __shared__ unsigned sm[256];
    int b = blockIdx.x, t = threadIdx.x;
    int i0 = b * SCAN_CHUNK + t;
    int i1 = i0 + 256;
    unsigned s = 0;
    if (i0 < nrows) s += g_cnt[i0];
    if (i1 < nrows) s += g_cnt[i1];
    sm[t] = s;
    __syncthreads();
    for (int off = 128; off; off >>= 1) {
        if (t < off) sm[t] += sm[t + off];
        __syncthreads();
    }
    if (t == 0) g_partials[b] = sm[0];
}

__global__ void __launch_bounds__(256)
scan_partials_kernel(int nb, int nrows, int nE) {
    __shared__ unsigned bufA[256], bufB[256];
    int t = threadIdx.x;
    bufA[t] = (t < nb) ? g_partials[t] : 0u;
    __syncthreads();
    unsigned* src = bufA;
    unsigned* dst = bufB;
    for (int off = 1; off < 256; off <<= 1) {
        unsigned v = src[t];
        if (t >= off) v += src[t - off];
        dst[t] = v;
        __syncthreads();
        unsigned* tmp = src; src = dst; dst = tmp;
    }
    unsigned excl = (t == 0) ? 0u : src[t - 1];
    if (t < nb) g_partials[t] = excl;
    if (t == 0) g_rowstart[nrows] = (unsigned)nE;
}

__global__ void __launch_bounds__(256)
offsets_kernel(int nrows) {
    __shared__ unsigned bufA[256], bufB[256];
    int b = blockIdx.x, t = threadIdx.x;
    int e0 = b * SCAN_CHUNK + 2 * t;
    int e1 = e0 + 1;
    unsigned c0 = (e0 < nrows) ? g_cnt[e0] : 0u;
    unsigned c1 = (e1 < nrows) ? g_cnt[e1] : 0u;
    bufA[t] = c0 + c1;
    __syncthreads();
    unsigned* src = bufA;
    unsigned* dst = bufB;
    for (int off = 1; off < 256; off <<= 1) {
        unsigned v = src[t];
        if (t >= off) v += src[t - off];
        dst[t] = v;
        __syncthreads();
        unsigned* tmp = src; src = dst; dst = tmp;
    }
    unsigned excl = (t == 0) ? 0u : src[t - 1];
    unsigned base = g_partials[b] + excl;
    if (e0 < nrows) { g_rowstart[e0] = base;      g_cursor[e0] = base; }
    if (e1 < nrows) { g_rowstart[e1] = base + c0; g_cursor[e1] = base + c0; }
}

__global__ void __launch_bounds__(256)
bin_kernel(const float* __restrict__ vals,
           const int*   __restrict__ rows,
           const int*   __restrict__ cols,
           int nE) {
    int e = blockIdx.x * blockDim.x + threadIdx.x;
    if (e >= nE) return;
    int r = __ldg(rows + e);
    unsigned pos = atomicAdd(&g_cursor[r], 1u);
    g_bins[pos] = make_uint2(__float_as_uint(__ldg(vals + e)),
                             (unsigned)__ldg(cols + e));
}

// ---------------------------------------------------------------------------
// Gather-reduce: one warp per output row. Lanes split the row's edges,
// accumulate 14 floats in registers, butterfly-reduce, lane 0 writes 56B.
// No atomics anywhere.
// ---------------------------------------------------------------------------
__global__ void __launch_bounds__(256)
gather_kernel(float* __restrict__ out, int nrows) {
    int w    = (blockIdx.x * blockDim.x + threadIdx.x) >> 5;
    int lane = threadIdx.x & 31;
    if (w >= nrows) return;

    unsigned start = g_rowstart[w];
    unsigned end   = g_rowstart[w + 1];

    float acc[ODIM];
#pragma unroll
    for (int j = 0; j < ODIM; j++) acc[j] = 0.f;

    for (unsigned i = start + lane; i < end; i += 32) {
        uint2 p = __ldg(&g_bins[i]);          // coalesced within warp
        float v = __uint_as_float(p.x);
        const float4* s = (const float4*)(g_support + (size_t)p.y * PAD);
        float4 s0 = __ldg(s + 0);
        float4 s1 = __ldg(s + 1);
        float4 s2 = __ldg(s + 2);
        float2 s3 = __ldg((const float2*)(s + 3));
        acc[0]  += v * s0.x;  acc[1]  += v * s0.y;
        acc[2]  += v * s0.z;  acc[3]  += v * s0.w;
        acc[4]  += v * s1.x;  acc[5]  += v * s1.y;
        acc[6]  += v * s1.z;  acc[7]  += v * s1.w;
        acc[8]  += v * s2.x;  acc[9]  += v * s2.y;
        acc[10] += v * s2.z;  acc[11] += v * s2.w;
        acc[12] += v * s3.x;  acc[13] += v * s3.y;
    }

#pragma unroll
    for (int off = 16; off; off >>= 1)
#pragma unroll
        for (int j = 0; j < ODIM; j++)
            acc[j] += __shfl_down_sync(0xffffffffu, acc[j], off);

    if (lane == 0) {
        float2* op = (float2*)(out + (size_t)w * ODIM);   // 8B-aligned (56|8)
#pragma unroll
        for (int k = 0; k < ODIM / 2; k++)
            op[k] = make_float2(acc[2 * k], acc[2 * k + 1]);
    }
}

// ---------------------------------------------------------------------------
extern "C" void kernel_launch(void* const* d_in, const int* in_sizes, int n_in,
                              void* d_out, int out_size) {
    const float* x    = (const float*)d_in[0];
    const float* W    = (const float*)d_in[1];
    const float* b    = (const float*)d_in[2];
    const float* vals = (const float*)d_in[3];
    const int*   rows = (const int*)d_in[4];
    const int*   cols = (const int*)d_in[5];
    float*       out  = (float*)d_out;

    int nrows = in_sizes[0] / FEAT;
    int nE    = in_sizes[3];
    int nb    = (nrows + SCAN_CHUNK - 1) / SCAN_CHUNK;   // <= 256 for N<=131072

    cudaFuncSetAttribute(gemm_kernel,
                         cudaFuncAttributeMaxDynamicSharedMemorySize,
                         GEMM_SMEM_BYTES);

    int ntiles = (nrows + RPB - 1) / RPB;
    int ggrid = ntiles < GEMM_GRID ? ntiles : GEMM_GRID;

    transpose_w_kernel<<<(ODIM * FEAT + 255) / 256, 256>>>(W);
    zero_cnt_kernel<<<(nrows + 255) / 256, 256>>>(nrows);
    count_kernel<<<(nE + 255) / 256, 256>>>(rows, nE);
    partial_kernel<<<nb, 256>>>(nrows);
    scan_partials_kernel<<<1, 256>>>(nb, nrows, nE);
    offsets_kernel<<<nb, 256>>>(nrows);
    bin_kernel<<<(nE + 255) / 256, 256>>>(vals, rows, cols, nE);
    gemm_kernel<<<ggrid, TPB, GEMM_SMEM_BYTES>>>(x, b, nrows);
    gather_kernel<<<(nrows * 32 + 255) / 256, 256>>>(out, nrows);
}